// round 4
// baseline (speedup 1.0000x reference)
#include <cuda_runtime.h>

// Problem constants
#define BB      4096
#define NHID    512
#define BR      32
#define N2      1024            // level-2 node count (label >> 5)
#define WSTRIDE (NHID * BR)     // floats per node = 16384

// Scratch (allocation-free rule: __device__ globals)
__device__ int d_count[N2];
__device__ int d_start[N2 + 1];
__device__ int d_cursor[N2];
__device__ int d_order[BB];

// ---------------------------------------------------------------------------
// Sort-by-level-2-node pipeline (tiny kernels)
// ---------------------------------------------------------------------------
__global__ void k_zero() {
    int i = blockIdx.x * blockDim.x + threadIdx.x;
    if (i < N2) d_count[i] = 0;
}

__global__ void k_hist(const int* __restrict__ labels) {
    int i = blockIdx.x * blockDim.x + threadIdx.x;
    if (i < BB) atomicAdd(&d_count[(labels[i] >> 5) & (N2 - 1)], 1);
}

__global__ void k_scan() {
    __shared__ int s[N2];
    int t = threadIdx.x;
    int c = d_count[t];
    s[t] = c;
    __syncthreads();
    for (int off = 1; off < N2; off <<= 1) {
        int v = (t >= off) ? s[t - off] : 0;
        __syncthreads();
        s[t] += v;
        __syncthreads();
    }
    d_start[t + 1] = s[t];
    if (t == 0) d_start[0] = 0;
    d_cursor[t] = s[t] - c;   // exclusive prefix: scatter cursor
}

__global__ void k_scatter(const int* __restrict__ labels) {
    int i = blockIdx.x * blockDim.x + threadIdx.x;
    if (i < BB) {
        int n = (labels[i] >> 5) & (N2 - 1);
        int pos = atomicAdd(&d_cursor[n], 1);
        d_order[pos] = i;
    }
}

// ---------------------------------------------------------------------------
// Main kernel: one block per level-2 node; all 3 levels computed per sample
// ---------------------------------------------------------------------------
struct Smem {
    float xs[8][NHID];       // staged inputs for up to 8 samples (16 KB)
    float part[8][8][BR];    // [warp][sample][col] partial dot products (8 KB)
    float pr[8];             // per-sample running probability product
    int   sb[8];             // sample ids
    int   steps[3][8];       // per-level step index
};

template <int S>
__device__ __forceinline__ void chunk_body(
    int base,
    const float* __restrict__ x, const int* __restrict__ labels,
    const float* __restrict__ W, float* __restrict__ out,
    int n0, int n1, int n2, Smem& sm)
{
    int tid  = threadIdx.x;
    int lane = tid & 31;
    int w    = tid >> 5;

    if (tid < S) {
        int bi = d_order[base + tid];
        sm.sb[tid] = bi;
        int lab = labels[bi];
        sm.steps[0][tid] = (lab >> 10) & 31;
        sm.steps[1][tid] = (lab >> 5) & 31;
        sm.steps[2][tid] = lab & 31;
        sm.pr[tid] = 1.0f;
    }
    __syncthreads();

    // Stage S input rows (float4 coalesced)
    constexpr int TOT4 = S * (NHID / 4);
    for (int i = tid; i < TOT4; i += 256) {
        int s  = i >> 7;       // / (NHID/4) = 128
        int h4 = i & 127;
        reinterpret_cast<float4*>(sm.xs[s])[h4] =
            reinterpret_cast<const float4*>(x + (size_t)sm.sb[s] * NHID)[h4];
    }
    __syncthreads();

    for (int d = 0; d < 3; d++) {
        int node = (d == 0) ? n0 : (d == 1 ? n1 : n2);
        // Warp w covers h in [w*64, w*64+64); lane = output column
        const float* Wp = W + (size_t)node * WSTRIDE + (w * 64) * BR + lane;
        float acc[S];
        #pragma unroll
        for (int s = 0; s < S; s++) acc[s] = 0.0f;

        #pragma unroll 2
        for (int q = 0; q < 16; q++) {
            float w0 = Wp[(q * 4 + 0) * BR];
            float w1 = Wp[(q * 4 + 1) * BR];
            float w2 = Wp[(q * 4 + 2) * BR];
            float w3 = Wp[(q * 4 + 3) * BR];
            int h = w * 64 + q * 4;
            #pragma unroll
            for (int s = 0; s < S; s++) {
                float4 xv = *reinterpret_cast<const float4*>(&sm.xs[s][h]);
                acc[s] = fmaf(xv.x, w0, acc[s]);
                acc[s] = fmaf(xv.y, w1, acc[s]);
                acc[s] = fmaf(xv.z, w2, acc[s]);
                acc[s] = fmaf(xv.w, w3, acc[s]);
            }
        }
        #pragma unroll
        for (int s = 0; s < S; s++) sm.part[w][s][lane] = acc[s];
        __syncthreads();

        if (w < S) {
            int s = w;
            float logit = 0.0f;
            #pragma unroll
            for (int ww = 0; ww < 8; ww++) logit += sm.part[ww][s][lane];
            // softmax over 32 columns (one warp, lane = column)
            float mx = logit;
            #pragma unroll
            for (int o = 16; o > 0; o >>= 1)
                mx = fmaxf(mx, __shfl_xor_sync(0xffffffffu, mx, o));
            float e = __expf(logit - mx);
            float sum = e;
            #pragma unroll
            for (int o = 16; o > 0; o >>= 1)
                sum += __shfl_xor_sync(0xffffffffu, sum, o);
            float esel = __shfl_sync(0xffffffffu, e, sm.steps[d][s]);
            if (lane == 0) sm.pr[s] *= esel / sum;
        }
        __syncthreads();
    }

    if (tid < S) out[sm.sb[tid]] = sm.pr[tid];
    __syncthreads();   // protect smem before next chunk
}

__global__ void __launch_bounds__(256)
k_main(const float* __restrict__ x, const int* __restrict__ labels,
       const float* __restrict__ W, float* __restrict__ out)
{
    __shared__ Smem sm;
    int j = blockIdx.x;                  // level-2 local node
    int begin = d_start[j];
    int end   = d_start[j + 1];
    if (begin >= end) return;

    int n0 = 0;
    int n1 = 1 + (j >> 5);
    int n2 = 33 + j;

    for (int base = begin; base < end; base += 8) {
        int nS = min(8, end - base);
        switch (nS) {
            case 8: chunk_body<8>(base, x, labels, W, out, n0, n1, n2, sm); break;
            case 7: chunk_body<7>(base, x, labels, W, out, n0, n1, n2, sm); break;
            case 6: chunk_body<6>(base, x, labels, W, out, n0, n1, n2, sm); break;
            case 5: chunk_body<5>(base, x, labels, W, out, n0, n1, n2, sm); break;
            case 4: chunk_body<4>(base, x, labels, W, out, n0, n1, n2, sm); break;
            case 3: chunk_body<3>(base, x, labels, W, out, n0, n1, n2, sm); break;
            case 2: chunk_body<2>(base, x, labels, W, out, n0, n1, n2, sm); break;
            default: chunk_body<1>(base, x, labels, W, out, n0, n1, n2, sm); break;
        }
    }
}

// ---------------------------------------------------------------------------
extern "C" void kernel_launch(void* const* d_in, const int* in_sizes, int n_in,
                              void* d_out, int out_size)
{
    const float* x      = (const float*)d_in[0];   // (4096, 512) f32
    const int*   labels = (const int*)d_in[1];     // (4096,) i32
    const float* W      = (const float*)d_in[2];   // (1057, 512, 32) f32
    float* out = (float*)d_out;                    // (4096,) f32

    k_zero<<<4, 256>>>();
    k_hist<<<16, 256>>>(labels);
    k_scan<<<1, N2>>>();
    k_scatter<<<16, 256>>>(labels);
    k_main<<<N2, 256>>>(x, labels, W, out);
}

// round 5
// speedup vs baseline: 1.1082x; 1.1082x over previous
#include <cuda_runtime.h>

// Problem constants
#define BB      4096
#define NHID    512
#define BR      32
#define N2      1024            // level-2 node count (label >> 5)
#define WSTRIDE (NHID * BR)     // floats per node = 16384

// Scratch (allocation-free rule: __device__ globals)
__device__ int d_start[N2 + 1];
__device__ int d_order[BB];

// ---------------------------------------------------------------------------
// Fused setup: histogram + scan + scatter in ONE single-block kernel
// ---------------------------------------------------------------------------
__global__ void __launch_bounds__(N2)
k_setup(const int* __restrict__ labels) {
    __shared__ int cnt[N2];
    __shared__ int cur[N2];
    int t = threadIdx.x;
    cnt[t] = 0;
    __syncthreads();

    // histogram (4096 labels, 1024 threads -> 4 each), smem atomics
    #pragma unroll
    for (int r = 0; r < BB / N2; r++) {
        int lab = labels[t + r * N2];
        atomicAdd(&cnt[(lab >> 5) & (N2 - 1)], 1);
    }
    __syncthreads();

    int c = cnt[t];
    // Hillis-Steele inclusive scan in cnt[]
    for (int off = 1; off < N2; off <<= 1) {
        int v = (t >= off) ? cnt[t - off] : 0;
        __syncthreads();
        cnt[t] += v;
        __syncthreads();
    }
    d_start[t + 1] = cnt[t];
    if (t == 0) d_start[0] = 0;
    cur[t] = cnt[t] - c;            // exclusive prefix = scatter cursor
    __syncthreads();

    // scatter sample ids
    #pragma unroll
    for (int r = 0; r < BB / N2; r++) {
        int i = t + r * N2;
        int n = (labels[i] >> 5) & (N2 - 1);
        int pos = atomicAdd(&cur[n], 1);
        d_order[pos] = i;
    }
}

// ---------------------------------------------------------------------------
// Main kernel: one block per level-2 node; all 3 levels fused
// ---------------------------------------------------------------------------
struct Smem {
    float xs[8][NHID];          // staged inputs, up to 8 samples (16 KB)
    float part[3][8][8][BR];    // [level][warp][sample][col] partials (24 KB)
    float probs[3][8];          // per-level selected probability
    int   sb[8];                // sample ids
    int   steps[3][8];          // per-level step index
};

template <int S>
__device__ __forceinline__ void chunk_body(
    int base,
    const float* __restrict__ x, const int* __restrict__ labels,
    const float* __restrict__ W, float* __restrict__ out,
    int n0, int n1, int n2, Smem& sm)
{
    int tid  = threadIdx.x;
    int lane = tid & 31;
    int w    = tid >> 5;
    int c4   = lane & 7;        // column group: columns 4*c4 .. 4*c4+3
    int rg   = lane >> 3;       // row-in-group: 0..3

    if (tid < S) {
        int bi = d_order[base + tid];
        sm.sb[tid] = bi;
        int lab = labels[bi];
        sm.steps[0][tid] = (lab >> 10) & 31;
        sm.steps[1][tid] = (lab >> 5) & 31;
        sm.steps[2][tid] = lab & 31;
    }
    __syncthreads();

    // Stage S input rows (float4 coalesced)
    for (int i = tid; i < S * (NHID / 4); i += 256) {
        int s  = i >> 7;
        int h4 = i & 127;
        reinterpret_cast<float4*>(sm.xs[s])[h4] =
            reinterpret_cast<const float4*>(x + (size_t)sm.sb[s] * NHID)[h4];
    }
    __syncthreads();

    // ---- All 3 levels: GEMV partials with LDG.128 weight loads ----
    const int nodes[3] = {n0, n1, n2};
    #pragma unroll
    for (int d = 0; d < 3; d++) {
        // warp w covers h in [w*64, w*64+64) as 16 blocks of 4 rows;
        // lane loads float4 = 4 consecutive columns of row (hb*4 + rg)
        const float4* Wp4 = reinterpret_cast<const float4*>(
            W + (size_t)nodes[d] * WSTRIDE + (size_t)w * 64 * BR);

        float acc[S][4];
        #pragma unroll
        for (int s = 0; s < S; s++) {
            acc[s][0] = 0.f; acc[s][1] = 0.f; acc[s][2] = 0.f; acc[s][3] = 0.f;
        }

        #pragma unroll 4
        for (int hb = 0; hb < 16; hb++) {
            float4 wv = Wp4[hb * 32 + lane];
            int h = w * 64 + hb * 4 + rg;
            #pragma unroll
            for (int s = 0; s < S; s++) {
                float xv = sm.xs[s][h];
                acc[s][0] = fmaf(xv, wv.x, acc[s][0]);
                acc[s][1] = fmaf(xv, wv.y, acc[s][1]);
                acc[s][2] = fmaf(xv, wv.z, acc[s][2]);
                acc[s][3] = fmaf(xv, wv.w, acc[s][3]);
            }
        }

        // reduce across the 4 row-groups (lanes differing in bits 3,4)
        #pragma unroll
        for (int s = 0; s < S; s++) {
            #pragma unroll
            for (int k = 0; k < 4; k++) {
                acc[s][k] += __shfl_xor_sync(0xffffffffu, acc[s][k], 8);
                acc[s][k] += __shfl_xor_sync(0xffffffffu, acc[s][k], 16);
            }
        }
        if (rg == 0) {
            #pragma unroll
            for (int s = 0; s < S; s++) {
                *reinterpret_cast<float4*>(&sm.part[d][w][s][c4 * 4]) =
                    make_float4(acc[s][0], acc[s][1], acc[s][2], acc[s][3]);
            }
        }
    }
    __syncthreads();

    // ---- Softmax: 3*S independent tasks spread over 8 warps ----
    for (int task = w; task < 3 * S; task += 8) {
        int d = task / S;
        int s = task - d * S;
        float logit = 0.0f;
        #pragma unroll
        for (int ww = 0; ww < 8; ww++) logit += sm.part[d][ww][s][lane];

        float mx = logit;
        #pragma unroll
        for (int o = 16; o > 0; o >>= 1)
            mx = fmaxf(mx, __shfl_xor_sync(0xffffffffu, mx, o));
        float e = __expf(logit - mx);
        float sum = e;
        #pragma unroll
        for (int o = 16; o > 0; o >>= 1)
            sum += __shfl_xor_sync(0xffffffffu, sum, o);
        float esel = __shfl_sync(0xffffffffu, e, sm.steps[d][s]);
        if (lane == 0) sm.probs[d][s] = esel / sum;
    }
    __syncthreads();

    if (tid < S)
        out[sm.sb[tid]] = sm.probs[0][tid] * sm.probs[1][tid] * sm.probs[2][tid];
    __syncthreads();   // protect smem before next chunk
}

__global__ void __launch_bounds__(256)
k_main(const float* __restrict__ x, const int* __restrict__ labels,
       const float* __restrict__ W, float* __restrict__ out)
{
    __shared__ Smem sm;
    int j = blockIdx.x;                  // level-2 local node
    int begin = d_start[j];
    int end   = d_start[j + 1];
    if (begin >= end) return;

    int n0 = 0;
    int n1 = 1 + (j >> 5);
    int n2 = 33 + j;

    for (int base = begin; base < end; base += 8) {
        int nS = min(8, end - base);
        switch (nS) {
            case 8: chunk_body<8>(base, x, labels, W, out, n0, n1, n2, sm); break;
            case 7: chunk_body<7>(base, x, labels, W, out, n0, n1, n2, sm); break;
            case 6: chunk_body<6>(base, x, labels, W, out, n0, n1, n2, sm); break;
            case 5: chunk_body<5>(base, x, labels, W, out, n0, n1, n2, sm); break;
            case 4: chunk_body<4>(base, x, labels, W, out, n0, n1, n2, sm); break;
            case 3: chunk_body<3>(base, x, labels, W, out, n0, n1, n2, sm); break;
            case 2: chunk_body<2>(base, x, labels, W, out, n0, n1, n2, sm); break;
            default: chunk_body<1>(base, x, labels, W, out, n0, n1, n2, sm); break;
        }
    }
}

// ---------------------------------------------------------------------------
extern "C" void kernel_launch(void* const* d_in, const int* in_sizes, int n_in,
                              void* d_out, int out_size)
{
    const float* x      = (const float*)d_in[0];   // (4096, 512) f32
    const int*   labels = (const int*)d_in[1];     // (4096,) i32
    const float* W      = (const float*)d_in[2];   // (1057, 512, 32) f32
    float* out = (float*)d_out;                    // (4096,) f32

    k_setup<<<1, N2>>>(labels);
    k_main<<<N2, 256>>>(x, labels, W, out);
}

// round 7
// speedup vs baseline: 1.3554x; 1.2230x over previous
#include <cuda_runtime.h>

// Problem constants
#define BB      4096
#define NHID    512
#define BR      32
#define N2      1024            // level-2 node count (label >> 5)
#define WSTRIDE (NHID * BR)     // floats per node = 16384
#define MAXT    2592            // max tasks: 512 (L0) + 544 (L1) + 1536 (L2)

// Scratch (allocation-free rule: __device__ globals)
__device__ int   d_start[N2 + 1];
__device__ int   d_order[BB];
__device__ int4  d_tasks[MAXT];     // {node, base, cnt, level}
__device__ int   d_ntasks;
__device__ float d_probs[3 * BB];   // [level][sample]

// ---------------------------------------------------------------------------
// Fused setup: histogram + scan + scatter + task-list build (ONE block)
// ---------------------------------------------------------------------------
__global__ void __launch_bounds__(N2)
k_setup(const int* __restrict__ labels) {
    __shared__ int cnt[N2];
    __shared__ int cur[N2];
    __shared__ int ctr;
    int t = threadIdx.x;
    cnt[t] = 0;
    if (t == 0) ctr = 512;          // tasks 0..511 reserved for level 0
    __syncthreads();

    // histogram over level-2 nodes (smem atomics)
    #pragma unroll
    for (int r = 0; r < BB / N2; r++)
        atomicAdd(&cnt[(labels[t + r * N2] >> 5) & (N2 - 1)], 1);
    __syncthreads();

    int c = cnt[t];
    // inclusive scan
    for (int off = 1; off < N2; off <<= 1) {
        int v = (t >= off) ? cnt[t - off] : 0;
        __syncthreads();
        cnt[t] += v;
        __syncthreads();
    }
    d_start[t + 1] = cnt[t];
    if (t == 0) d_start[0] = 0;
    cur[t] = cnt[t] - c;            // exclusive prefix = scatter cursor
    __syncthreads();

    // scatter sample ids into node-sorted order
    #pragma unroll
    for (int r = 0; r < BB / N2; r++) {
        int i = t + r * N2;
        int n = (labels[i] >> 5) & (N2 - 1);
        d_order[atomicAdd(&cur[n], 1)] = i;
    }
    __syncthreads();

    // ---- build task list ----
    // level 0: 512 fixed tasks (node 0, any 8 samples each)
    if (t < 512) d_tasks[t] = make_int4(0, t * 8, 8, 0);

    // level 2: node t covers sorted range [start[t], start[t+1])
    {
        int s = cnt[t] - c;         // exclusive prefix  (= d_start[t])
        int e = cnt[t];             // inclusive         (= d_start[t+1])
        int n = e - s;
        if (n > 0) {
            int k = (n + 7) >> 3;
            int pos = atomicAdd(&ctr, k);
            for (int i = 0; i < k; i++) {
                int b = s + i * 8;
                d_tasks[pos + i] = make_int4(33 + t, b, min(8, e - b), 2);
            }
        }
    }

    // level 1: node m covers level-2 nodes [32m, 32m+32)
    __syncthreads();                // d_start fully written
    if (t < 32) {
        int s = d_start[t * 32];
        int e = d_start[t * 32 + 32];
        int n = e - s;
        if (n > 0) {
            int k = (n + 7) >> 3;
            int pos = atomicAdd(&ctr, k);
            for (int i = 0; i < k; i++) {
                int b = s + i * 8;
                d_tasks[pos + i] = make_int4(1 + t, b, min(8, e - b), 1);
            }
        }
    }
    __syncthreads();
    if (t == 0) d_ntasks = ctr;
}

// ---------------------------------------------------------------------------
// Main kernel: one block per task (single node, single level, <=8 samples)
// ---------------------------------------------------------------------------
struct Smem {
    float xs[8][NHID];          // staged inputs (16 KB)
    float part[8][8][BR];       // [warp][sample][col] partials (8 KB)
    int   sb[8];
    int   steps[8];
};

template <int S>
__device__ __forceinline__ void task_body(
    int node, int base, int level,
    const float* __restrict__ x, const int* __restrict__ labels,
    const float* __restrict__ W, Smem& sm)
{
    int tid  = threadIdx.x;
    int lane = tid & 31;
    int w    = tid >> 5;
    int c4   = lane & 7;        // column group (4 cols)
    int rg   = lane >> 3;       // row-in-group 0..3

    if (tid < S) {
        int bi = d_order[base + tid];
        sm.sb[tid] = bi;
        int lab = labels[bi];
        sm.steps[tid] = (lab >> (10 - 5 * level)) & 31;
    }
    __syncthreads();

    // stage S input rows (float4 coalesced)
    for (int i = tid; i < S * (NHID / 4); i += 256) {
        int s  = i >> 7;
        int h4 = i & 127;
        reinterpret_cast<float4*>(sm.xs[s])[h4] =
            reinterpret_cast<const float4*>(x + (size_t)sm.sb[s] * NHID)[h4];
    }
    __syncthreads();

    // GEMV partials: warp w covers h in [w*64, w*64+64), LDG.128 weights
    const float4* Wp4 = reinterpret_cast<const float4*>(
        W + (size_t)node * WSTRIDE + (size_t)w * 64 * BR);

    float acc[S][4];
    #pragma unroll
    for (int s = 0; s < S; s++) {
        acc[s][0] = 0.f; acc[s][1] = 0.f; acc[s][2] = 0.f; acc[s][3] = 0.f;
    }

    #pragma unroll 4
    for (int hb = 0; hb < 16; hb++) {
        float4 wv = Wp4[hb * 32 + lane];
        int h = w * 64 + hb * 4 + rg;
        #pragma unroll
        for (int s = 0; s < S; s++) {
            float xv = sm.xs[s][h];          // broadcast across c4 lanes
            acc[s][0] = fmaf(xv, wv.x, acc[s][0]);
            acc[s][1] = fmaf(xv, wv.y, acc[s][1]);
            acc[s][2] = fmaf(xv, wv.z, acc[s][2]);
            acc[s][3] = fmaf(xv, wv.w, acc[s][3]);
        }
    }

    // reduce across the 4 row-groups (lane bits 3,4)
    #pragma unroll
    for (int s = 0; s < S; s++) {
        #pragma unroll
        for (int k = 0; k < 4; k++) {
            acc[s][k] += __shfl_xor_sync(0xffffffffu, acc[s][k], 8);
            acc[s][k] += __shfl_xor_sync(0xffffffffu, acc[s][k], 16);
        }
    }
    if (rg == 0) {
        #pragma unroll
        for (int s = 0; s < S; s++)
            *reinterpret_cast<float4*>(&sm.part[w][s][c4 * 4]) =
                make_float4(acc[s][0], acc[s][1], acc[s][2], acc[s][3]);
    }
    __syncthreads();

    // softmax: warp w handles sample w (w < S)
    if (w < S) {
        int s = w;
        float logit = 0.0f;
        #pragma unroll
        for (int ww = 0; ww < 8; ww++) logit += sm.part[ww][s][lane];

        float mx = logit;
        #pragma unroll
        for (int o = 16; o > 0; o >>= 1)
            mx = fmaxf(mx, __shfl_xor_sync(0xffffffffu, mx, o));
        float e = __expf(logit - mx);
        float sum = e;
        #pragma unroll
        for (int o = 16; o > 0; o >>= 1)
            sum += __shfl_xor_sync(0xffffffffu, sum, o);
        float esel = __shfl_sync(0xffffffffu, e, sm.steps[s]);
        if (lane == 0) d_probs[level * BB + sm.sb[s]] = esel / sum;
    }
}

__global__ void __launch_bounds__(256)
k_main(const float* __restrict__ x, const int* __restrict__ labels,
       const float* __restrict__ W)
{
    __shared__ Smem sm;
    int idx = blockIdx.x;
    if (idx >= d_ntasks) return;
    int4 tk = d_tasks[idx];
    int node = tk.x, base = tk.y, cnt = tk.z, level = tk.w;

    switch (cnt) {
        case 8: task_body<8>(node, base, level, x, labels, W, sm); break;
        case 7: task_body<7>(node, base, level, x, labels, W, sm); break;
        case 6: task_body<6>(node, base, level, x, labels, W, sm); break;
        case 5: task_body<5>(node, base, level, x, labels, W, sm); break;
        case 4: task_body<4>(node, base, level, x, labels, W, sm); break;
        case 3: task_body<3>(node, base, level, x, labels, W, sm); break;
        case 2: task_body<2>(node, base, level, x, labels, W, sm); break;
        default: task_body<1>(node, base, level, x, labels, W, sm); break;
    }
}

// ---------------------------------------------------------------------------
__global__ void k_combine(float* __restrict__ out) {
    int i = blockIdx.x * blockDim.x + threadIdx.x;
    if (i < BB)
        out[i] = d_probs[i] * d_probs[BB + i] * d_probs[2 * BB + i];
}

// ---------------------------------------------------------------------------
extern "C" void kernel_launch(void* const* d_in, const int* in_sizes, int n_in,
                              void* d_out, int out_size)
{
    const float* x      = (const float*)d_in[0];   // (4096, 512) f32
    const int*   labels = (const int*)d_in[1];     // (4096,) i32
    const float* W      = (const float*)d_in[2];   // (1057, 512, 32) f32
    float* out = (float*)d_out;                    // (4096,) f32

    k_setup<<<1, N2>>>(labels);
    k_main<<<MAXT, 256>>>(x, labels, W);
    k_combine<<<16, 256>>>(out);
}